// round 7
// baseline (speedup 1.0000x reference)
#include <cuda_runtime.h>

#define BB    32
#define NIN   2048
#define NHID  512
#define NOUT  10
#define TLEN  350
#define KSRM  100
#define KREF  32
#define THETA 10.0f
#define TT    35            // timesteps per GEMM1 window (350 = 10*35)
#define NWIN  (TLEN / TT)   // 10
#define NW    (NIN / 32)    // 64
#define HW    (NHID / 32)   // 16
#define CH    16            // weight rows per staged chunk
#define NCHK  (NIN / CH)    // 128
#define NST   3             // cp.async ring stages
#define CC    25            // layer1 tile (100 = 4*25)
#define NCH   (TLEN / CC)   // 14
#define RING  5

// ---------------- device scratch ----------------
__device__ float    g_W1T[NIN * NHID];          // 4 MB, W1 transposed [n][m]
__device__ unsigned g_bits1[BB * TLEN * NW];    // packed spikes [b][t][w]
__device__ float    g_z1[BB * TLEN * NHID];     // [b][t][m]
__device__ unsigned g_s1b[BB * TLEN * HW];      // packed layer-1 spikes

extern __shared__ char sm_raw[];

// ---------------- K1: transpose W1 [NHID][NIN] -> [NIN][NHID] ------------
__global__ void k_transpose(const float* __restrict__ W1) {
    __shared__ float tile[32][33];
    int bx = blockIdx.x * 32, by = blockIdx.y * 32;
    int tx = threadIdx.x, ty = threadIdx.y;
    #pragma unroll
    for (int j = 0; j < 32; j += 8)
        tile[ty + j][tx] = W1[(by + ty + j) * NIN + bx + tx];
    __syncthreads();
    #pragma unroll
    for (int j = 0; j < 32; j += 8)
        g_W1T[(bx + ty + j) * NHID + (by + tx)] = tile[tx][ty + j];
}

// ---------------- K0: pack input spikes (float2 over t) ------------------
__global__ void k_pack(const float* __restrict__ x) {
    int b = blockIdx.y;
    int w = blockIdx.x;
    const float* xb = x + ((size_t)b * NIN + w * 32) * TLEN;
    for (int k = threadIdx.x; k < TLEN / 2; k += blockDim.x) {
        int t = k * 2;
        unsigned w0 = 0, w1 = 0;
        #pragma unroll
        for (int j = 0; j < 32; j++) {
            float2 v = *(const float2*)(xb + j * TLEN + t);
            w0 |= (v.x > 0.5f) ? (1u << j) : 0u;
            w1 |= (v.y > 0.5f) ? (1u << j) : 0u;
        }
        g_bits1[(b * TLEN + t    ) * NW + w] = w0;
        g_bits1[(b * TLEN + t + 1) * NW + w] = w1;
    }
}

// ---------------- dummy (ncu launch-slot alignment) ----------------------
__global__ void k_dummy() {}

// ---------------- K2: sparse GEMM, register acc, 3-stage cp.async --------
// CTA = (window of 35 t, b). 256 threads, thread owns 2 adjacent m.
// acc[35] as packed f32x2 in registers. Masks pre-split to ushort per
// (chunk, t): immediate-offset LDS.U16 in the hot loop. One barrier/chunk.
__global__ __launch_bounds__(256) void k_gemm1() {
    float*          stage = (float*)sm_raw;                        // [NST][CH*NHID] 96 KB
    unsigned short* hmask = (unsigned short*)(sm_raw + NST * CH * NHID * 4); // [NCHK][TT]

    int b   = blockIdx.y;
    int t0  = blockIdx.x * TT;
    int tid = threadIdx.x;

    // pre-split column masks: hmask[c][t] = 16 rows' spikes at time t0+t
    for (int i = tid; i < NCHK * TT; i += 256) {
        int c = i / TT, t = i - c * TT;
        unsigned word = g_bits1[(b * TLEN + t0 + t) * NW + (c >> 1)];
        hmask[i] = (unsigned short)(word >> ((c & 1) * 16));
    }

    unsigned long long acc[TT];
    #pragma unroll
    for (int t = 0; t < TT; t++) acc[t] = 0ull;

    const char* wsrc = (const char*)g_W1T;

    // cp.async chunk c -> stage s (8 x 16B per thread = 32 KB)
    #define ISSUE_CHUNK(c, s) do {                                           \
        unsigned _dst = (unsigned)__cvta_generic_to_shared(                  \
            stage + (s) * (CH * NHID)) + tid * 16;                           \
        const char* _src = wsrc + (size_t)(c) * (CH * NHID * 4) + tid * 16;  \
        _Pragma("unroll")                                                    \
        for (int k = 0; k < 8; k++)                                          \
            asm volatile("cp.async.cg.shared.global [%0], [%1], 16;"         \
                         :: "r"(_dst + k * 4096), "l"(_src + k * 4096)       \
                         : "memory");                                        \
        asm volatile("cp.async.commit_group;" ::: "memory");                 \
    } while (0)

    ISSUE_CHUNK(0, 0);
    ISSUE_CHUNK(1, 1);

    int sb = 0;   // stage being computed
    int ib = 2;   // stage to issue next into
    for (int c = 0; c < NCHK; c++) {
        if (c + 2 < NCHK)
            asm volatile("cp.async.wait_group 1;" ::: "memory");
        else
            asm volatile("cp.async.wait_group 0;" ::: "memory");
        __syncthreads();   // chunk c visible CTA-wide; all past compute(c-1)

        if (c + 2 < NCHK) {
            ISSUE_CHUNK(c + 2, ib);
            ib = (ib == NST - 1) ? 0 : ib + 1;
        }

        const unsigned long long* st2 =
            (const unsigned long long*)(stage + sb * (CH * NHID)) + tid;
        const unsigned short* hc = hmask + c * TT;

        #pragma unroll
        for (int t = 0; t < TT; t++) {
            unsigned m = hc[t];                  // LDS.U16, immediate offset
            while (m) {
                int j = __ffs(m) - 1; m &= m - 1;
                unsigned long long wv = st2[j * 256];   // LDS.64 conflict-free
                asm("add.rn.f32x2 %0, %0, %1;" : "+l"(acc[t]) : "l"(wv));
            }
        }
        sb = (sb == NST - 1) ? 0 : sb + 1;
    }
    #undef ISSUE_CHUNK

    float2* zo = (float2*)(g_z1 + ((size_t)b * TLEN + t0) * NHID);
    #pragma unroll
    for (int t = 0; t < TT; t++) {
        float2 v;
        v.x = __uint_as_float((unsigned)(acc[t] & 0xFFFFFFFFull));
        v.y = __uint_as_float((unsigned)(acc[t] >> 32));
        zo[t * 256 + tid] = v;                   // coalesced
    }
}

// ---------------- K3: layer-1 SRM + spike (smem ring) --------------------
__global__ void k_layer1() {
    float* ring  = (float*)sm_raw;                  // [RING][CC*128]
    float* srefk = (float*)sm_raw + RING * CC * 128;

    int b   = blockIdx.y;
    int m0  = blockIdx.x * 128;
    int tid = threadIdx.x;
    if (tid < KREF)
        srefk[tid] = -2.0f * THETA * (float)tid * expf(1.0f - (float)tid);

    const float r    = expf(-0.1f);
    const float rK   = expf(-10.0f);
    const float KrK  = 100.0f * rK;
    const float Ceps = expf(1.0f) * 0.1f;

    const float* zb = g_z1 + (size_t)b * TLEN * NHID + m0;

    float A = 0.f, Y = 0.f;
    unsigned hist = 0;
    int wbase = (b * TLEN) * HW + (m0 >> 5) + (tid >> 5);

    for (int c = 0; c < NCH; c++) {
        float* tile = ring + (c % RING) * (CC * 128);
        __syncthreads();
        #pragma unroll
        for (int i = 0; i < CC; i++)
            tile[i * 128 + tid] = zb[(size_t)(c * CC + i) * NHID + tid];
        __syncthreads();

        const float* tprev = ring + ((c + 1) % RING) * (CC * 128); // slot c-4
        #pragma unroll
        for (int i = 0; i < CC; i++) {
            float xz = tile[i * 128 + tid];
            float xo = (c >= 4) ? tprev[i * 128 + tid] : 0.f;
            float Yn = r * (Y + A) - KrK * xo;
            A = r * A + xz - rK * xo;
            Y = Yn;
            float u = Ceps * Y;

            float refr = 0.f;
            unsigned hb = hist;
            while (hb) { int k = __ffs(hb) - 1; hb &= hb - 1; refr += srefk[k + 1]; }

            bool s = (u + refr >= THETA);
            hist = ((hist << 1) | (s ? 1u : 0u)) & 0x7FFFFFFFu;

            unsigned bal = __ballot_sync(0xFFFFFFFFu, s);
            if ((tid & 31) == 0)
                g_s1b[wbase + (c * CC + i) * HW] = bal;
        }
    }
}

// ---------------- K4: fused gemm2 + layer-2 SRM + spike ------------------
__global__ __launch_bounds__(352) void k_out(const float* __restrict__ W2,
                                             float* __restrict__ out) {
    __shared__ float w2t[NHID * NOUT];
    __shared__ float q[NOUT * TLEN];
    __shared__ float srefk[KREF];

    int b = blockIdx.x, tid = threadIdx.x;
    for (int i = tid; i < NHID * NOUT; i += blockDim.x) {
        int o = i / NHID, m = i % NHID;
        w2t[m * NOUT + o] = W2[i];
    }
    if (tid < KREF)
        srefk[tid] = -2.0f * THETA * (float)tid * expf(1.0f - (float)tid);
    __syncthreads();

    if (tid < TLEN) {
        int t = tid;
        float a[NOUT];
        #pragma unroll
        for (int o = 0; o < NOUT; o++) a[o] = 0.f;
        #pragma unroll
        for (int w = 0; w < HW; w++) {
            unsigned bits = g_s1b[(b * TLEN + t) * HW + w];
            while (bits) {
                int m = w * 32 + __ffs(bits) - 1;
                bits &= bits - 1;
                #pragma unroll
                for (int o = 0; o < NOUT; o++) a[o] += w2t[m * NOUT + o];
            }
        }
        #pragma unroll
        for (int o = 0; o < NOUT; o++) q[o * TLEN + t] = a[o];
    }
    __syncthreads();

    if (tid < NOUT) {
        const float r    = expf(-0.1f);
        const float rK   = expf(-10.0f);
        const float KrK  = 100.0f * rK;
        const float Ceps = expf(1.0f) * 0.1f;

        const float* qq = q + tid * TLEN;
        float* so = out + ((size_t)b * NOUT + tid) * TLEN;

        float A = 0.f, Y = 0.f;
        unsigned hist = 0;
        for (int t = 0; t < TLEN; t++) {
            float xz = qq[t];
            float xo = (t >= KSRM) ? qq[t - KSRM] : 0.f;
            float Yn = r * (Y + A) - KrK * xo;
            A = r * A + xz - rK * xo;
            Y = Yn;
            float u = Ceps * Y;

            float refr = 0.f;
            unsigned hb = hist;
            while (hb) { int k = __ffs(hb) - 1; hb &= hb - 1; refr += srefk[k + 1]; }

            bool s = (u + refr >= THETA);
            hist = ((hist << 1) | (s ? 1u : 0u)) & 0x7FFFFFFFu;
            so[t] = s ? 1.0f : 0.0f;
        }
    }
}

// ---------------- launch ----------------
extern "C" void kernel_launch(void* const* d_in, const int* in_sizes, int n_in,
                              void* d_out, int out_size) {
    const float* x  = (const float*)d_in[0];   // [32, 2048, 350]
    const float* W1 = (const float*)d_in[1];   // [512, 2048]
    const float* W2 = (const float*)d_in[2];   // [10, 512]
    float* out = (float*)d_out;                // [32, 10, 350]

    const int SMEM_G1 = NST * CH * NHID * 4 + NCHK * TT * 2;  // 107,264 B
    const int SMEM_L1 = (RING * CC * 128 + KREF) * 4;         // 64,128 B
    cudaFuncSetAttribute(k_gemm1, cudaFuncAttributeMaxDynamicSharedMemorySize,
                         SMEM_G1);
    cudaFuncSetAttribute(k_layer1, cudaFuncAttributeMaxDynamicSharedMemorySize,
                         SMEM_L1);

    k_transpose<<<dim3(NIN / 32, NHID / 32), dim3(32, 8)>>>(W1);   // 1
    k_pack<<<dim3(NW, BB), 128>>>(x);                              // 2
    k_dummy<<<1, 32>>>();                                          // 3
    k_gemm1<<<dim3(NWIN, BB), 256, SMEM_G1>>>();                   // 4 (ncu slot)
    k_layer1<<<dim3(NHID / 128, BB), 128, SMEM_L1>>>();            // 5
    k_out<<<BB, 352>>>(W2, out);                                   // 6
}

// round 8
// speedup vs baseline: 1.3385x; 1.3385x over previous
#include <cuda_runtime.h>

#define BB    32
#define NIN   2048
#define NHID  512
#define NOUT  10
#define TLEN  350
#define KSRM  100
#define KREF  32
#define THETA 10.0f
#define TT    35            // timesteps per GEMM1 window (350 = 10*35)
#define NWIN  (TLEN / TT)   // 10
#define NW    (NIN / 32)    // 64
#define HW    (NHID / 32)   // 16
#define CH    16            // weight rows per staged chunk
#define NCHK  (NIN / CH)    // 128
#define TG    18            // timesteps per thread-group (group0:18, group1:17)
#define CC    25            // layer1 tile (100 = 4*25)
#define NCH   (TLEN / CC)   // 14
#define RING  5

// ---------------- device scratch ----------------
__device__ float    g_W1T[NIN * NHID];          // 4 MB, W1 transposed [n][m]
__device__ unsigned g_bits1[BB * TLEN * NW];    // packed spikes [b][t][w]
__device__ float    g_z1[BB * TLEN * NHID];     // [b][t][m]
__device__ unsigned g_s1b[BB * TLEN * HW];      // packed layer-1 spikes

extern __shared__ char sm_raw[];

// ---------------- K1: transpose W1 [NHID][NIN] -> [NIN][NHID] ------------
__global__ void k_transpose(const float* __restrict__ W1) {
    __shared__ float tile[32][33];
    int bx = blockIdx.x * 32, by = blockIdx.y * 32;
    int tx = threadIdx.x, ty = threadIdx.y;
    #pragma unroll
    for (int j = 0; j < 32; j += 8)
        tile[ty + j][tx] = W1[(by + ty + j) * NIN + bx + tx];
    __syncthreads();
    #pragma unroll
    for (int j = 0; j < 32; j += 8)
        g_W1T[(bx + ty + j) * NHID + (by + tx)] = tile[tx][ty + j];
}

// ---------------- K0: pack input spikes (float2 over t) ------------------
__global__ void k_pack(const float* __restrict__ x) {
    int b = blockIdx.y;
    int w = blockIdx.x;
    const float* xb = x + ((size_t)b * NIN + w * 32) * TLEN;
    for (int k = threadIdx.x; k < TLEN / 2; k += blockDim.x) {
        int t = k * 2;
        unsigned w0 = 0, w1 = 0;
        #pragma unroll
        for (int j = 0; j < 32; j++) {
            float2 v = *(const float2*)(xb + j * TLEN + t);
            w0 |= (v.x > 0.5f) ? (1u << j) : 0u;
            w1 |= (v.y > 0.5f) ? (1u << j) : 0u;
        }
        g_bits1[(b * TLEN + t    ) * NW + w] = w0;
        g_bits1[(b * TLEN + t + 1) * NW + w] = w1;
    }
}

// ---------------- dummy (ncu launch-slot alignment) ----------------------
__global__ void k_dummy() {}

// ---------------- K2: sparse GEMM, t-split groups, float4 acc ------------
// CTA = (window of 35 t, b). 256 threads in 2 t-groups of 128; each thread
// owns 4 adjacent m's. acc[18] float4 in registers. Weights staged via
// cp.async double buffer (R6 structure, known good).
__global__ __launch_bounds__(256) void k_gemm1() {
    float*    stage = (float*)sm_raw;                          // [2][CH*NHID] 64 KB
    unsigned* colm  = (unsigned*)(sm_raw + 2 * CH * NHID * 4); // [TT][NW] 8.75 KB

    int b    = blockIdx.y;
    int t0   = blockIdx.x * TT;
    int tid  = threadIdx.x;
    int tg   = tid >> 7;          // t-group 0/1
    int lid  = tid & 127;         // m-slot (owns m = 4*lid .. 4*lid+3)
    int tbeg = tg * TG;           // group0: t 0..17, group1: t 18..34

    // column masks for this window ([t][w] contiguous in g_bits1)
    for (int i = tid; i < TT * NW; i += 256)
        colm[i] = g_bits1[(b * TLEN + t0) * NW + i];

    float4 acc[TG];
    #pragma unroll
    for (int i = 0; i < TG; i++) acc[i] = make_float4(0.f, 0.f, 0.f, 0.f);

    const char* wsrc = (const char*)g_W1T;

    // cp.async copy of chunk c into buffer c&1 (8 x 16B per thread = 32 KB)
    #define ISSUE_CHUNK(c) do {                                              \
        unsigned _dst = (unsigned)__cvta_generic_to_shared(                  \
            stage + ((c) & 1) * (CH * NHID)) + tid * 16;                     \
        const char* _src = wsrc + (size_t)(c) * (CH * NHID * 4) + tid * 16;  \
        _Pragma("unroll")                                                    \
        for (int k = 0; k < 8; k++)                                          \
            asm volatile("cp.async.cg.shared.global [%0], [%1], 16;"         \
                         :: "r"(_dst + k * 4096), "l"(_src + k * 4096)       \
                         : "memory");                                        \
        asm volatile("cp.async.commit_group;" ::: "memory");                 \
    } while (0)

    ISSUE_CHUNK(0);

    for (int c = 0; c < NCHK; c++) {
        if (c) __syncthreads();            // everyone done reading buf (c+1)&1
        if (c + 1 < NCHK) {
            ISSUE_CHUNK(c + 1);
            asm volatile("cp.async.wait_group 1;" ::: "memory");
        } else {
            asm volatile("cp.async.wait_group 0;" ::: "memory");
        }
        __syncthreads();                   // chunk c (and colm on c==0) visible

        const float4* st = (const float4*)(stage + (c & 1) * (CH * NHID)) + lid;
        int wi = c >> 1, sh = (c & 1) * 16;

        #pragma unroll
        for (int i = 0; i < TG; i++) {
            int t = tbeg + i;
            unsigned m = (t < TT) ? ((colm[t * NW + wi] >> sh) & 0xFFFFu) : 0u;
            while (m) {
                int j = __ffs(m) - 1; m &= m - 1;
                float4 wv = st[j * 128];       // LDS.128, conflict-free
                acc[i].x += wv.x;
                acc[i].y += wv.y;
                acc[i].z += wv.z;
                acc[i].w += wv.w;
            }
        }
    }
    #undef ISSUE_CHUNK

    float4* zo = (float4*)(g_z1 + ((size_t)b * TLEN + t0) * NHID);
    #pragma unroll
    for (int i = 0; i < TG; i++) {
        int t = tbeg + i;
        if (t < TT) zo[t * 128 + lid] = acc[i];    // coalesced 16B stores
    }
}

// ---------------- K3: layer-1 SRM + spike (smem ring) --------------------
__global__ void k_layer1() {
    float* ring  = (float*)sm_raw;                  // [RING][CC*128]
    float* srefk = (float*)sm_raw + RING * CC * 128;

    int b   = blockIdx.y;
    int m0  = blockIdx.x * 128;
    int tid = threadIdx.x;
    if (tid < KREF)
        srefk[tid] = -2.0f * THETA * (float)tid * expf(1.0f - (float)tid);

    const float r    = expf(-0.1f);
    const float rK   = expf(-10.0f);
    const float KrK  = 100.0f * rK;
    const float Ceps = expf(1.0f) * 0.1f;

    const float* zb = g_z1 + (size_t)b * TLEN * NHID + m0;

    float A = 0.f, Y = 0.f;
    unsigned hist = 0;
    int wbase = (b * TLEN) * HW + (m0 >> 5) + (tid >> 5);

    for (int c = 0; c < NCH; c++) {
        float* tile = ring + (c % RING) * (CC * 128);
        __syncthreads();
        #pragma unroll
        for (int i = 0; i < CC; i++)
            tile[i * 128 + tid] = zb[(size_t)(c * CC + i) * NHID + tid];
        __syncthreads();

        const float* tprev = ring + ((c + 1) % RING) * (CC * 128); // slot c-4
        #pragma unroll
        for (int i = 0; i < CC; i++) {
            float xz = tile[i * 128 + tid];
            float xo = (c >= 4) ? tprev[i * 128 + tid] : 0.f;
            float Yn = r * (Y + A) - KrK * xo;
            A = r * A + xz - rK * xo;
            Y = Yn;
            float u = Ceps * Y;

            float refr = 0.f;
            unsigned hb = hist;
            while (hb) { int k = __ffs(hb) - 1; hb &= hb - 1; refr += srefk[k + 1]; }

            bool s = (u + refr >= THETA);
            hist = ((hist << 1) | (s ? 1u : 0u)) & 0x7FFFFFFFu;

            unsigned bal = __ballot_sync(0xFFFFFFFFu, s);
            if ((tid & 31) == 0)
                g_s1b[wbase + (c * CC + i) * HW] = bal;
        }
    }
}

// ---------------- K4: fused gemm2 + layer-2 SRM + spike ------------------
__global__ __launch_bounds__(352) void k_out(const float* __restrict__ W2,
                                             float* __restrict__ out) {
    __shared__ float w2t[NHID * NOUT];
    __shared__ float q[NOUT * TLEN];
    __shared__ float srefk[KREF];

    int b = blockIdx.x, tid = threadIdx.x;
    for (int i = tid; i < NHID * NOUT; i += blockDim.x) {
        int o = i / NHID, m = i % NHID;
        w2t[m * NOUT + o] = W2[i];
    }
    if (tid < KREF)
        srefk[tid] = -2.0f * THETA * (float)tid * expf(1.0f - (float)tid);
    __syncthreads();

    if (tid < TLEN) {
        int t = tid;
        float a[NOUT];
        #pragma unroll
        for (int o = 0; o < NOUT; o++) a[o] = 0.f;
        #pragma unroll
        for (int w = 0; w < HW; w++) {
            unsigned bits = g_s1b[(b * TLEN + t) * HW + w];
            while (bits) {
                int m = w * 32 + __ffs(bits) - 1;
                bits &= bits - 1;
                #pragma unroll
                for (int o = 0; o < NOUT; o++) a[o] += w2t[m * NOUT + o];
            }
        }
        #pragma unroll
        for (int o = 0; o < NOUT; o++) q[o * TLEN + t] = a[o];
    }
    __syncthreads();

    if (tid < NOUT) {
        const float r    = expf(-0.1f);
        const float rK   = expf(-10.0f);
        const float KrK  = 100.0f * rK;
        const float Ceps = expf(1.0f) * 0.1f;

        const float* qq = q + tid * TLEN;
        float* so = out + ((size_t)b * NOUT + tid) * TLEN;

        float A = 0.f, Y = 0.f;
        unsigned hist = 0;
        for (int t = 0; t < TLEN; t++) {
            float xz = qq[t];
            float xo = (t >= KSRM) ? qq[t - KSRM] : 0.f;
            float Yn = r * (Y + A) - KrK * xo;
            A = r * A + xz - rK * xo;
            Y = Yn;
            float u = Ceps * Y;

            float refr = 0.f;
            unsigned hb = hist;
            while (hb) { int k = __ffs(hb) - 1; hb &= hb - 1; refr += srefk[k + 1]; }

            bool s = (u + refr >= THETA);
            hist = ((hist << 1) | (s ? 1u : 0u)) & 0x7FFFFFFFu;
            so[t] = s ? 1.0f : 0.0f;
        }
    }
}

// ---------------- launch ----------------
extern "C" void kernel_launch(void* const* d_in, const int* in_sizes, int n_in,
                              void* d_out, int out_size) {
    const float* x  = (const float*)d_in[0];   // [32, 2048, 350]
    const float* W1 = (const float*)d_in[1];   // [512, 2048]
    const float* W2 = (const float*)d_in[2];   // [10, 512]
    float* out = (float*)d_out;                // [32, 10, 350]

    const int SMEM_G1 = 2 * CH * NHID * 4 + TT * NW * 4;   // 74,496 B
    const int SMEM_L1 = (RING * CC * 128 + KREF) * 4;      // 64,128 B
    cudaFuncSetAttribute(k_gemm1, cudaFuncAttributeMaxDynamicSharedMemorySize,
                         SMEM_G1);
    cudaFuncSetAttribute(k_layer1, cudaFuncAttributeMaxDynamicSharedMemorySize,
                         SMEM_L1);

    k_transpose<<<dim3(NIN / 32, NHID / 32), dim3(32, 8)>>>(W1);   // 1
    k_pack<<<dim3(NW, BB), 128>>>(x);                              // 2
    k_dummy<<<1, 32>>>();                                          // 3
    k_gemm1<<<dim3(NWIN, BB), 256, SMEM_G1>>>();                   // 4 (ncu slot)
    k_layer1<<<dim3(NHID / 128, BB), 128, SMEM_L1>>>();            // 5
    k_out<<<BB, 352>>>(W2, out);                                   // 6
}

// round 9
// speedup vs baseline: 1.3690x; 1.0228x over previous
#include <cuda_runtime.h>

#define BB    32
#define NIN   2048
#define NHID  512
#define NOUT  10
#define TLEN  350
#define KSRM  100
#define KREF  32
#define THETA 10.0f
#define TT    35            // timesteps per GEMM1 window (350 = 10*35)
#define NWIN  (TLEN / TT)   // 10
#define NW    (NIN / 32)    // 64
#define HW    (NHID / 32)   // 16
#define CH    32            // weight rows per staged chunk (= one mask word)
#define NCHK  (NIN / CH)    // 64
#define CC    25            // layer1 tile (100 = 4*25)
#define NCH   (TLEN / CC)   // 14
#define RING  5

// ---------------- device scratch ----------------
__device__ float    g_W1T[NIN * NHID];          // 4 MB, W1 transposed [n][m]
__device__ unsigned g_bits1[BB * TLEN * NW];    // packed spikes [b][t][w]
__device__ float    g_z1[BB * TLEN * NHID];     // [b][t][m]
__device__ unsigned g_s1b[BB * TLEN * HW];      // packed layer-1 spikes

extern __shared__ char sm_raw[];

// ---------------- K1: transpose W1 [NHID][NIN] -> [NIN][NHID] ------------
__global__ void k_transpose(const float* __restrict__ W1) {
    __shared__ float tile[32][33];
    int bx = blockIdx.x * 32, by = blockIdx.y * 32;
    int tx = threadIdx.x, ty = threadIdx.y;
    #pragma unroll
    for (int j = 0; j < 32; j += 8)
        tile[ty + j][tx] = W1[(by + ty + j) * NIN + bx + tx];
    __syncthreads();
    #pragma unroll
    for (int j = 0; j < 32; j += 8)
        g_W1T[(bx + ty + j) * NHID + (by + tx)] = tile[tx][ty + j];
}

// ---------------- K0: pack input spikes (float2 over t) ------------------
__global__ void k_pack(const float* __restrict__ x) {
    int b = blockIdx.y;
    int w = blockIdx.x;
    const float* xb = x + ((size_t)b * NIN + w * 32) * TLEN;
    for (int k = threadIdx.x; k < TLEN / 2; k += blockDim.x) {
        int t = k * 2;
        unsigned w0 = 0, w1 = 0;
        #pragma unroll
        for (int j = 0; j < 32; j++) {
            float2 v = *(const float2*)(xb + j * TLEN + t);
            w0 |= (v.x > 0.5f) ? (1u << j) : 0u;
            w1 |= (v.y > 0.5f) ? (1u << j) : 0u;
        }
        g_bits1[(b * TLEN + t    ) * NW + w] = w0;
        g_bits1[(b * TLEN + t + 1) * NW + w] = w1;
    }
}

// ---------------- dummy (ncu launch-slot alignment) ----------------------
__global__ void k_dummy() {}

// ---------------- K2: sparse GEMM, single-buffer CH=32, 3 CTAs/SM --------
// CTA = (window of 35 t, b). 256 threads, thread owns 2 adjacent m (float2).
// acc[35] in registers (t statically unrolled). Single 64 KB weight stage,
// full 32-bit mask words; inter-CTA overlap (3 CTAs/SM) hides cp.async wait.
__global__ __launch_bounds__(256) void k_gemm1() {
    float*    stage = (float*)sm_raw;                      // [CH*NHID] 64 KB
    unsigned* colm  = (unsigned*)(sm_raw + CH * NHID * 4); // [TT][NW] 8.75 KB

    int b   = blockIdx.y;
    int t0  = blockIdx.x * TT;
    int tid = threadIdx.x;

    // column masks for this window ([t][w] contiguous in g_bits1)
    for (int i = tid; i < TT * NW; i += 256)
        colm[i] = g_bits1[(b * TLEN + t0) * NW + i];

    float2 acc[TT];
    #pragma unroll
    for (int t = 0; t < TT; t++) acc[t] = make_float2(0.f, 0.f);

    const char* wsrc = (const char*)g_W1T;
    unsigned sdst = (unsigned)__cvta_generic_to_shared(stage) + tid * 16;

    for (int c = 0; c < NCHK; c++) {
        __syncthreads();                       // all done reading chunk c-1
        {                                      // cp.async chunk c (64 KB)
            const char* src = wsrc + (size_t)c * (CH * NHID * 4) + tid * 16;
            #pragma unroll
            for (int k = 0; k < 16; k++)
                asm volatile("cp.async.cg.shared.global [%0], [%1], 16;"
                             :: "r"(sdst + k * 4096), "l"(src + k * 4096)
                             : "memory");
            asm volatile("cp.async.commit_group;" ::: "memory");
            asm volatile("cp.async.wait_group 0;" ::: "memory");
        }
        __syncthreads();                       // chunk c visible CTA-wide

        const float2* st = (const float2*)stage + tid;

        #pragma unroll
        for (int t = 0; t < TT; t++) {
            unsigned m = colm[t * NW + c];     // full 32-bit word, no shift
            while (m) {
                int j = __ffs(m) - 1; m &= m - 1;
                float2 wv = st[j * 256];       // LDS.64, conflict-free
                acc[t].x += wv.x;
                acc[t].y += wv.y;
            }
        }
    }

    float2* zo = (float2*)(g_z1 + ((size_t)b * TLEN + t0) * NHID);
    #pragma unroll
    for (int t = 0; t < TT; t++)
        zo[t * 256 + tid] = acc[t];            // coalesced
}

// ---------------- K3: layer-1 SRM + spike (smem ring) --------------------
__global__ void k_layer1() {
    float* ring  = (float*)sm_raw;                  // [RING][CC*128]
    float* srefk = (float*)sm_raw + RING * CC * 128;

    int b   = blockIdx.y;
    int m0  = blockIdx.x * 128;
    int tid = threadIdx.x;
    if (tid < KREF)
        srefk[tid] = -2.0f * THETA * (float)tid * expf(1.0f - (float)tid);

    const float r    = expf(-0.1f);
    const float rK   = expf(-10.0f);
    const float KrK  = 100.0f * rK;
    const float Ceps = expf(1.0f) * 0.1f;

    const float* zb = g_z1 + (size_t)b * TLEN * NHID + m0;

    float A = 0.f, Y = 0.f;
    unsigned hist = 0;
    int wbase = (b * TLEN) * HW + (m0 >> 5) + (tid >> 5);

    for (int c = 0; c < NCH; c++) {
        float* tile = ring + (c % RING) * (CC * 128);
        __syncthreads();
        #pragma unroll
        for (int i = 0; i < CC; i++)
            tile[i * 128 + tid] = zb[(size_t)(c * CC + i) * NHID + tid];
        __syncthreads();

        const float* tprev = ring + ((c + 1) % RING) * (CC * 128); // slot c-4
        #pragma unroll
        for (int i = 0; i < CC; i++) {
            float xz = tile[i * 128 + tid];
            float xo = (c >= 4) ? tprev[i * 128 + tid] : 0.f;
            float Yn = r * (Y + A) - KrK * xo;
            A = r * A + xz - rK * xo;
            Y = Yn;
            float u = Ceps * Y;

            float refr = 0.f;
            unsigned hb = hist;
            while (hb) { int k = __ffs(hb) - 1; hb &= hb - 1; refr += srefk[k + 1]; }

            bool s = (u + refr >= THETA);
            hist = ((hist << 1) | (s ? 1u : 0u)) & 0x7FFFFFFFu;

            unsigned bal = __ballot_sync(0xFFFFFFFFu, s);
            if ((tid & 31) == 0)
                g_s1b[wbase + (c * CC + i) * HW] = bal;
        }
    }
}

// ---------------- K4: fused gemm2 + layer-2 SRM + spike ------------------
__global__ __launch_bounds__(352) void k_out(const float* __restrict__ W2,
                                             float* __restrict__ out) {
    __shared__ float w2t[NHID * NOUT];
    __shared__ float q[NOUT * TLEN];
    __shared__ float srefk[KREF];

    int b = blockIdx.x, tid = threadIdx.x;
    for (int i = tid; i < NHID * NOUT; i += blockDim.x) {
        int o = i / NHID, m = i % NHID;
        w2t[m * NOUT + o] = W2[i];
    }
    if (tid < KREF)
        srefk[tid] = -2.0f * THETA * (float)tid * expf(1.0f - (float)tid);
    __syncthreads();

    if (tid < TLEN) {
        int t = tid;
        float a[NOUT];
        #pragma unroll
        for (int o = 0; o < NOUT; o++) a[o] = 0.f;
        #pragma unroll
        for (int w = 0; w < HW; w++) {
            unsigned bits = g_s1b[(b * TLEN + t) * HW + w];
            while (bits) {
                int m = w * 32 + __ffs(bits) - 1;
                bits &= bits - 1;
                #pragma unroll
                for (int o = 0; o < NOUT; o++) a[o] += w2t[m * NOUT + o];
            }
        }
        #pragma unroll
        for (int o = 0; o < NOUT; o++) q[o * TLEN + t] = a[o];
    }
    __syncthreads();

    if (tid < NOUT) {
        const float r    = expf(-0.1f);
        const float rK   = expf(-10.0f);
        const float KrK  = 100.0f * rK;
        const float Ceps = expf(1.0f) * 0.1f;

        const float* qq = q + tid * TLEN;
        float* so = out + ((size_t)b * NOUT + tid) * TLEN;

        float A = 0.f, Y = 0.f;
        unsigned hist = 0;
        for (int t = 0; t < TLEN; t++) {
            float xz = qq[t];
            float xo = (t >= KSRM) ? qq[t - KSRM] : 0.f;
            float Yn = r * (Y + A) - KrK * xo;
            A = r * A + xz - rK * xo;
            Y = Yn;
            float u = Ceps * Y;

            float refr = 0.f;
            unsigned hb = hist;
            while (hb) { int k = __ffs(hb) - 1; hb &= hb - 1; refr += srefk[k + 1]; }

            bool s = (u + refr >= THETA);
            hist = ((hist << 1) | (s ? 1u : 0u)) & 0x7FFFFFFFu;
            so[t] = s ? 1.0f : 0.0f;
        }
    }
}

// ---------------- launch ----------------
extern "C" void kernel_launch(void* const* d_in, const int* in_sizes, int n_in,
                              void* d_out, int out_size) {
    const float* x  = (const float*)d_in[0];   // [32, 2048, 350]
    const float* W1 = (const float*)d_in[1];   // [512, 2048]
    const float* W2 = (const float*)d_in[2];   // [10, 512]
    float* out = (float*)d_out;                // [32, 10, 350]

    const int SMEM_G1 = CH * NHID * 4 + TT * NW * 4;       // 74,496 B (1 buf)
    const int SMEM_L1 = (RING * CC * 128 + KREF) * 4;      // 64,128 B
    cudaFuncSetAttribute(k_gemm1, cudaFuncAttributeMaxDynamicSharedMemorySize,
                         SMEM_G1);
    cudaFuncSetAttribute(k_layer1, cudaFuncAttributeMaxDynamicSharedMemorySize,
                         SMEM_L1);

    k_transpose<<<dim3(NIN / 32, NHID / 32), dim3(32, 8)>>>(W1);   // 1
    k_pack<<<dim3(NW, BB), 128>>>(x);                              // 2
    k_dummy<<<1, 32>>>();                                          // 3
    k_gemm1<<<dim3(NWIN, BB), 256, SMEM_G1>>>();                   // 4 (ncu slot)
    k_layer1<<<dim3(NHID / 128, BB), 128, SMEM_L1>>>();            // 5
    k_out<<<BB, 352>>>(W2, out);                                   // 6
}

// round 10
// speedup vs baseline: 2.0905x; 1.5271x over previous
#include <cuda_runtime.h>

#define BB    32
#define NIN   2048
#define NHID  512
#define NOUT  10
#define TLEN  350
#define KSRM  100
#define KREF  32
#define THETA 10.0f
#define TT    25            // timesteps per GEMM1 window (350 = 14*25)
#define NWIN  (TLEN / TT)   // 14
#define NW    (NIN / 32)    // 64
#define HW    (NHID / 32)   // 16
#define CH    16            // weight rows per staged chunk
#define NCHK  (NIN / CH)    // 128
#define CC    25            // layer1 tile (100 = 4*25)
#define NCH   (TLEN / CC)   // 14
#define RING  5

// ---------------- device scratch ----------------
__device__ float    g_W1T[NIN * NHID];          // 4 MB, W1 transposed [n][m]
__device__ unsigned g_bits1[BB * TLEN * NW];    // packed spikes [b][t][w]
__device__ float    g_z1[BB * TLEN * NHID];     // [b][t][m]
__device__ unsigned g_s1b[BB * TLEN * HW];      // packed layer-1 spikes

extern __shared__ char sm_raw[];

// ---------------- K1: transpose W1 [NHID][NIN] -> [NIN][NHID] ------------
__global__ void k_transpose(const float* __restrict__ W1) {
    __shared__ float tile[32][33];
    int bx = blockIdx.x * 32, by = blockIdx.y * 32;
    int tx = threadIdx.x, ty = threadIdx.y;
    #pragma unroll
    for (int j = 0; j < 32; j += 8)
        tile[ty + j][tx] = W1[(by + ty + j) * NIN + bx + tx];
    __syncthreads();
    #pragma unroll
    for (int j = 0; j < 32; j += 8)
        g_W1T[(bx + ty + j) * NHID + (by + tx)] = tile[tx][ty + j];
}

// ---------------- K0: pack input spikes (float2 over t) ------------------
__global__ void k_pack(const float* __restrict__ x) {
    int b = blockIdx.y;
    int w = blockIdx.x;
    const float* xb = x + ((size_t)b * NIN + w * 32) * TLEN;
    for (int k = threadIdx.x; k < TLEN / 2; k += blockDim.x) {
        int t = k * 2;
        unsigned w0 = 0, w1 = 0;
        #pragma unroll
        for (int j = 0; j < 32; j++) {
            float2 v = *(const float2*)(xb + j * TLEN + t);
            w0 |= (v.x > 0.5f) ? (1u << j) : 0u;
            w1 |= (v.y > 0.5f) ? (1u << j) : 0u;
        }
        g_bits1[(b * TLEN + t    ) * NW + w] = w0;
        g_bits1[(b * TLEN + t + 1) * NW + w] = w1;
    }
}

// ---------------- dummy (ncu launch-slot alignment) ----------------------
__global__ void k_dummy() {}

// ---------------- K2: sparse GEMM, TT=25, 3 CTAs/SM, double buffer -------
// CTA = (window of 25 t, b). 256 threads, thread owns 2 adjacent m (float2).
// acc[25] in registers. R6-proven double-buffered cp.async weight staging.
// Grid 448 at 3 CTAs/SM => 1.009 waves, 24 warps/SM.
__global__ __launch_bounds__(256, 3) void k_gemm1() {
    float*    stage = (float*)sm_raw;                          // [2][CH*NHID] 64 KB
    unsigned* colm  = (unsigned*)(sm_raw + 2 * CH * NHID * 4); // [TT][NW] 6.25 KB

    int b   = blockIdx.y;
    int t0  = blockIdx.x * TT;
    int tid = threadIdx.x;

    // column masks for this window ([t][w] contiguous in g_bits1)
    for (int i = tid; i < TT * NW; i += 256)
        colm[i] = g_bits1[(b * TLEN + t0) * NW + i];

    float2 acc[TT];
    #pragma unroll
    for (int t = 0; t < TT; t++) acc[t] = make_float2(0.f, 0.f);

    const char* wsrc = (const char*)g_W1T;

    // cp.async copy of chunk c into buffer c&1 (8 x 16B per thread = 32 KB)
    #define ISSUE_CHUNK(c) do {                                              \
        unsigned _dst = (unsigned)__cvta_generic_to_shared(                  \
            stage + ((c) & 1) * (CH * NHID)) + tid * 16;                     \
        const char* _src = wsrc + (size_t)(c) * (CH * NHID * 4) + tid * 16;  \
        _Pragma("unroll")                                                    \
        for (int k = 0; k < 8; k++)                                          \
            asm volatile("cp.async.cg.shared.global [%0], [%1], 16;"         \
                         :: "r"(_dst + k * 4096), "l"(_src + k * 4096)       \
                         : "memory");                                        \
        asm volatile("cp.async.commit_group;" ::: "memory");                 \
    } while (0)

    ISSUE_CHUNK(0);

    for (int c = 0; c < NCHK; c++) {
        if (c) __syncthreads();            // everyone done reading buf (c+1)&1
        if (c + 1 < NCHK) {
            ISSUE_CHUNK(c + 1);
            asm volatile("cp.async.wait_group 1;" ::: "memory");
        } else {
            asm volatile("cp.async.wait_group 0;" ::: "memory");
        }
        __syncthreads();                   // chunk c (and colm on c==0) visible

        const float2* st = (const float2*)(stage + (c & 1) * (CH * NHID)) + tid;
        int wi = c >> 1, sh = (c & 1) * 16;

        #pragma unroll
        for (int t = 0; t < TT; t++) {
            unsigned m = (colm[t * NW + wi] >> sh) & 0xFFFFu;
            while (m) {
                int j = __ffs(m) - 1; m &= m - 1;
                float2 wv = st[j * 256];   // LDS.64, conflict-free
                acc[t].x += wv.x;
                acc[t].y += wv.y;
            }
        }
    }
    #undef ISSUE_CHUNK

    float2* zo = (float2*)(g_z1 + ((size_t)b * TLEN + t0) * NHID);
    #pragma unroll
    for (int t = 0; t < TT; t++)
        zo[t * 256 + tid] = acc[t];        // coalesced
}

// ---------------- K3: layer-1 SRM + spike (smem ring) --------------------
__global__ void k_layer1() {
    float* ring  = (float*)sm_raw;                  // [RING][CC*128]
    float* srefk = (float*)sm_raw + RING * CC * 128;

    int b   = blockIdx.y;
    int m0  = blockIdx.x * 128;
    int tid = threadIdx.x;
    if (tid < KREF)
        srefk[tid] = -2.0f * THETA * (float)tid * expf(1.0f - (float)tid);

    const float r    = expf(-0.1f);
    const float rK   = expf(-10.0f);
    const float KrK  = 100.0f * rK;
    const float Ceps = expf(1.0f) * 0.1f;

    const float* zb = g_z1 + (size_t)b * TLEN * NHID + m0;

    float A = 0.f, Y = 0.f;
    unsigned hist = 0;
    int wbase = (b * TLEN) * HW + (m0 >> 5) + (tid >> 5);

    for (int c = 0; c < NCH; c++) {
        float* tile = ring + (c % RING) * (CC * 128);
        __syncthreads();
        #pragma unroll
        for (int i = 0; i < CC; i++)
            tile[i * 128 + tid] = zb[(size_t)(c * CC + i) * NHID + tid];
        __syncthreads();

        const float* tprev = ring + ((c + 1) % RING) * (CC * 128); // slot c-4
        #pragma unroll
        for (int i = 0; i < CC; i++) {
            float xz = tile[i * 128 + tid];
            float xo = (c >= 4) ? tprev[i * 128 + tid] : 0.f;
            float Yn = r * (Y + A) - KrK * xo;
            A = r * A + xz - rK * xo;
            Y = Yn;
            float u = Ceps * Y;

            float refr = 0.f;
            unsigned hb = hist;
            while (hb) { int k = __ffs(hb) - 1; hb &= hb - 1; refr += srefk[k + 1]; }

            bool s = (u + refr >= THETA);
            hist = ((hist << 1) | (s ? 1u : 0u)) & 0x7FFFFFFFu;

            unsigned bal = __ballot_sync(0xFFFFFFFFu, s);
            if ((tid & 31) == 0)
                g_s1b[wbase + (c * CC + i) * HW] = bal;
        }
    }
}

// ---------------- K4: fused gemm2 + layer-2 SRM + spike ------------------
__global__ __launch_bounds__(352) void k_out(const float* __restrict__ W2,
                                             float* __restrict__ out) {
    __shared__ float w2t[NHID * NOUT];
    __shared__ float q[NOUT * TLEN];
    __shared__ float srefk[KREF];

    int b = blockIdx.x, tid = threadIdx.x;
    for (int i = tid; i < NHID * NOUT; i += blockDim.x) {
        int o = i / NHID, m = i % NHID;
        w2t[m * NOUT + o] = W2[i];
    }
    if (tid < KREF)
        srefk[tid] = -2.0f * THETA * (float)tid * expf(1.0f - (float)tid);
    __syncthreads();

    if (tid < TLEN) {
        int t = tid;
        float a[NOUT];
        #pragma unroll
        for (int o = 0; o < NOUT; o++) a[o] = 0.f;
        #pragma unroll
        for (int w = 0; w < HW; w++) {
            unsigned bits = g_s1b[(b * TLEN + t) * HW + w];
            while (bits) {
                int m = w * 32 + __ffs(bits) - 1;
                bits &= bits - 1;
                #pragma unroll
                for (int o = 0; o < NOUT; o++) a[o] += w2t[m * NOUT + o];
            }
        }
        #pragma unroll
        for (int o = 0; o < NOUT; o++) q[o * TLEN + t] = a[o];
    }
    __syncthreads();

    if (tid < NOUT) {
        const float r    = expf(-0.1f);
        const float rK   = expf(-10.0f);
        const float KrK  = 100.0f * rK;
        const float Ceps = expf(1.0f) * 0.1f;

        const float* qq = q + tid * TLEN;
        float* so = out + ((size_t)b * NOUT + tid) * TLEN;

        float A = 0.f, Y = 0.f;
        unsigned hist = 0;
        for (int t = 0; t < TLEN; t++) {
            float xz = qq[t];
            float xo = (t >= KSRM) ? qq[t - KSRM] : 0.f;
            float Yn = r * (Y + A) - KrK * xo;
            A = r * A + xz - rK * xo;
            Y = Yn;
            float u = Ceps * Y;

            float refr = 0.f;
            unsigned hb = hist;
            while (hb) { int k = __ffs(hb) - 1; hb &= hb - 1; refr += srefk[k + 1]; }

            bool s = (u + refr >= THETA);
            hist = ((hist << 1) | (s ? 1u : 0u)) & 0x7FFFFFFFu;
            so[t] = s ? 1.0f : 0.0f;
        }
    }
}

// ---------------- launch ----------------
extern "C" void kernel_launch(void* const* d_in, const int* in_sizes, int n_in,
                              void* d_out, int out_size) {
    const float* x  = (const float*)d_in[0];   // [32, 2048, 350]
    const float* W1 = (const float*)d_in[1];   // [512, 2048]
    const float* W2 = (const float*)d_in[2];   // [10, 512]
    float* out = (float*)d_out;                // [32, 10, 350]

    const int SMEM_G1 = 2 * CH * NHID * 4 + TT * NW * 4;   // 71,936 B
    const int SMEM_L1 = (RING * CC * 128 + KREF) * 4;      // 64,128 B
    cudaFuncSetAttribute(k_gemm1, cudaFuncAttributeMaxDynamicSharedMemorySize,
                         SMEM_G1);
    cudaFuncSetAttribute(k_layer1, cudaFuncAttributeMaxDynamicSharedMemorySize,
                         SMEM_L1);

    k_transpose<<<dim3(NIN / 32, NHID / 32), dim3(32, 8)>>>(W1);   // 1
    k_pack<<<dim3(NW, BB), 128>>>(x);                              // 2
    k_dummy<<<1, 32>>>();                                          // 3
    k_gemm1<<<dim3(NWIN, BB), 256, SMEM_G1>>>();                   // 4 (ncu slot)
    k_layer1<<<dim3(NHID / 128, BB), 128, SMEM_L1>>>();            // 5
    k_out<<<BB, 352>>>(W2, out);                                   // 6
}

// round 11
// speedup vs baseline: 2.2850x; 1.0930x over previous
#include <cuda_runtime.h>

#define BB    32
#define NIN   2048
#define NHID  512
#define NOUT  10
#define TLEN  350
#define KSRM  100
#define KREF  32
#define THETA 10.0f
#define TT    25            // timesteps per GEMM1 window (350 = 14*25)
#define NWIN  (TLEN / TT)   // 14
#define NW    (NIN / 32)    // 64
#define HW    (NHID / 32)   // 16
#define CH    16            // weight rows per staged chunk
#define NCHK  (NIN / CH)    // 128
#define CC    25            // layer1 tile (100 = 4*25)
#define NCH   (TLEN / CC)   // 14
#define RING  5

// ---------------- device scratch ----------------
__device__ float    g_W1T[NIN * NHID];          // 4 MB, W1 transposed [n][m]
__device__ unsigned g_bits1[BB * TLEN * NW];    // packed spikes [b][t][w]
__device__ float    g_z1[BB * TLEN * NHID];     // [b][t][m]
__device__ unsigned g_s1b[BB * TLEN * HW];      // packed layer-1 spikes

extern __shared__ char sm_raw[];

// ---------------- K1: transpose W1 [NHID][NIN] -> [NIN][NHID] ------------
__global__ void k_transpose(const float* __restrict__ W1) {
    __shared__ float tile[32][33];
    int bx = blockIdx.x * 32, by = blockIdx.y * 32;
    int tx = threadIdx.x, ty = threadIdx.y;
    #pragma unroll
    for (int j = 0; j < 32; j += 8)
        tile[ty + j][tx] = W1[(by + ty + j) * NIN + bx + tx];
    __syncthreads();
    #pragma unroll
    for (int j = 0; j < 32; j += 8)
        g_W1T[(bx + ty + j) * NHID + (by + tx)] = tile[tx][ty + j];
}

// ---------------- K0: pack input spikes (float2 over t) ------------------
__global__ void k_pack(const float* __restrict__ x) {
    int b = blockIdx.y;
    int w = blockIdx.x;
    const float* xb = x + ((size_t)b * NIN + w * 32) * TLEN;
    for (int k = threadIdx.x; k < TLEN / 2; k += blockDim.x) {
        int t = k * 2;
        unsigned w0 = 0, w1 = 0;
        #pragma unroll
        for (int j = 0; j < 32; j++) {
            float2 v = *(const float2*)(xb + j * TLEN + t);
            w0 |= (v.x > 0.5f) ? (1u << j) : 0u;
            w1 |= (v.y > 0.5f) ? (1u << j) : 0u;
        }
        g_bits1[(b * TLEN + t    ) * NW + w] = w0;
        g_bits1[(b * TLEN + t + 1) * NW + w] = w1;
    }
}

// ---------------- dummy (ncu launch-slot alignment) ----------------------
__global__ void k_dummy() {}

// ---------------- K2: sparse GEMM, 128 thr x float4, 3 CTAs/SM -----------
// CTA = (window of 25 t, b). 128 threads, thread owns 4 adjacent m (float4).
// acc[25] float4 in registers. Double-buffered cp.async weight staging
// (proven R6/R10 protocol). Per event: 4 warps x 7 instr vs 8 x 6 before.
__global__ __launch_bounds__(128, 3) void k_gemm1() {
    float*    stage = (float*)sm_raw;                          // [2][CH*NHID] 64 KB
    unsigned* colm  = (unsigned*)(sm_raw + 2 * CH * NHID * 4); // [TT][NW] 6.25 KB

    int b   = blockIdx.y;
    int t0  = blockIdx.x * TT;
    int tid = threadIdx.x;

    // column masks for this window ([t][w] contiguous in g_bits1)
    for (int i = tid; i < TT * NW; i += 128)
        colm[i] = g_bits1[(b * TLEN + t0) * NW + i];

    float4 acc[TT];
    #pragma unroll
    for (int t = 0; t < TT; t++) acc[t] = make_float4(0.f, 0.f, 0.f, 0.f);

    const char* wsrc = (const char*)g_W1T;

    // cp.async copy of chunk c into buffer c&1 (16 x 16B per thread = 32 KB)
    #define ISSUE_CHUNK(c) do {                                              \
        unsigned _dst = (unsigned)__cvta_generic_to_shared(                  \
            stage + ((c) & 1) * (CH * NHID)) + tid * 16;                     \
        const char* _src = wsrc + (size_t)(c) * (CH * NHID * 4) + tid * 16;  \
        _Pragma("unroll")                                                    \
        for (int k = 0; k < 16; k++)                                         \
            asm volatile("cp.async.cg.shared.global [%0], [%1], 16;"         \
                         :: "r"(_dst + k * 2048), "l"(_src + k * 2048)       \
                         : "memory");                                        \
        asm volatile("cp.async.commit_group;" ::: "memory");                 \
    } while (0)

    ISSUE_CHUNK(0);

    for (int c = 0; c < NCHK; c++) {
        if (c) __syncthreads();            // everyone done reading buf (c+1)&1
        if (c + 1 < NCHK) {
            ISSUE_CHUNK(c + 1);
            asm volatile("cp.async.wait_group 1;" ::: "memory");
        } else {
            asm volatile("cp.async.wait_group 0;" ::: "memory");
        }
        __syncthreads();                   // chunk c (and colm on c==0) visible

        const float4* st = (const float4*)(stage + (c & 1) * (CH * NHID)) + tid;
        int wi = c >> 1, sh = (c & 1) * 16;

        #pragma unroll
        for (int t = 0; t < TT; t++) {
            unsigned m = (colm[t * NW + wi] >> sh) & 0xFFFFu;
            while (m) {
                int j = __ffs(m) - 1; m &= m - 1;
                float4 wv = st[j * 128];   // LDS.128, conflict-free
                acc[t].x += wv.x;
                acc[t].y += wv.y;
                acc[t].z += wv.z;
                acc[t].w += wv.w;
            }
        }
    }
    #undef ISSUE_CHUNK

    float4* zo = (float4*)(g_z1 + ((size_t)b * TLEN + t0) * NHID);
    #pragma unroll
    for (int t = 0; t < TT; t++)
        zo[t * 128 + tid] = acc[t];        // coalesced 16B stores
}

// ---------------- K3: layer-1 SRM + spike (smem ring) --------------------
__global__ void k_layer1() {
    float* ring  = (float*)sm_raw;                  // [RING][CC*128]
    float* srefk = (float*)sm_raw + RING * CC * 128;

    int b   = blockIdx.y;
    int m0  = blockIdx.x * 128;
    int tid = threadIdx.x;
    if (tid < KREF)
        srefk[tid] = -2.0f * THETA * (float)tid * expf(1.0f - (float)tid);

    const float r    = expf(-0.1f);
    const float rK   = expf(-10.0f);
    const float KrK  = 100.0f * rK;
    const float Ceps = expf(1.0f) * 0.1f;

    const float* zb = g_z1 + (size_t)b * TLEN * NHID + m0;

    float A = 0.f, Y = 0.f;
    unsigned hist = 0;
    int wbase = (b * TLEN) * HW + (m0 >> 5) + (tid >> 5);

    for (int c = 0; c < NCH; c++) {
        float* tile = ring + (c % RING) * (CC * 128);
        __syncthreads();
        #pragma unroll
        for (int i = 0; i < CC; i++)
            tile[i * 128 + tid] = zb[(size_t)(c * CC + i) * NHID + tid];
        __syncthreads();

        const float* tprev = ring + ((c + 1) % RING) * (CC * 128); // slot c-4
        #pragma unroll
        for (int i = 0; i < CC; i++) {
            float xz = tile[i * 128 + tid];
            float xo = (c >= 4) ? tprev[i * 128 + tid] : 0.f;
            float Yn = r * (Y + A) - KrK * xo;
            A = r * A + xz - rK * xo;
            Y = Yn;
            float u = Ceps * Y;

            float refr = 0.f;
            unsigned hb = hist;
            while (hb) { int k = __ffs(hb) - 1; hb &= hb - 1; refr += srefk[k + 1]; }

            bool s = (u + refr >= THETA);
            hist = ((hist << 1) | (s ? 1u : 0u)) & 0x7FFFFFFFu;

            unsigned bal = __ballot_sync(0xFFFFFFFFu, s);
            if ((tid & 31) == 0)
                g_s1b[wbase + (c * CC + i) * HW] = bal;
        }
    }
}

// ---------------- K4: fused gemm2 + layer-2 SRM + spike ------------------
__global__ __launch_bounds__(352) void k_out(const float* __restrict__ W2,
                                             float* __restrict__ out) {
    __shared__ float w2t[NHID * NOUT];
    __shared__ float q[NOUT * TLEN];
    __shared__ float srefk[KREF];

    int b = blockIdx.x, tid = threadIdx.x;
    for (int i = tid; i < NHID * NOUT; i += blockDim.x) {
        int o = i / NHID, m = i % NHID;
        w2t[m * NOUT + o] = W2[i];
    }
    if (tid < KREF)
        srefk[tid] = -2.0f * THETA * (float)tid * expf(1.0f - (float)tid);
    __syncthreads();

    if (tid < TLEN) {
        int t = tid;
        float a[NOUT];
        #pragma unroll
        for (int o = 0; o < NOUT; o++) a[o] = 0.f;
        #pragma unroll
        for (int w = 0; w < HW; w++) {
            unsigned bits = g_s1b[(b * TLEN + t) * HW + w];
            while (bits) {
                int m = w * 32 + __ffs(bits) - 1;
                bits &= bits - 1;
                #pragma unroll
                for (int o = 0; o < NOUT; o++) a[o] += w2t[m * NOUT + o];
            }
        }
        #pragma unroll
        for (int o = 0; o < NOUT; o++) q[o * TLEN + t] = a[o];
    }
    __syncthreads();

    if (tid < NOUT) {
        const float r    = expf(-0.1f);
        const float rK   = expf(-10.0f);
        const float KrK  = 100.0f * rK;
        const float Ceps = expf(1.0f) * 0.1f;

        const float* qq = q + tid * TLEN;
        float* so = out + ((size_t)b * NOUT + tid) * TLEN;

        float A = 0.f, Y = 0.f;
        unsigned hist = 0;
        for (int t = 0; t < TLEN; t++) {
            float xz = qq[t];
            float xo = (t >= KSRM) ? qq[t - KSRM] : 0.f;
            float Yn = r * (Y + A) - KrK * xo;
            A = r * A + xz - rK * xo;
            Y = Yn;
            float u = Ceps * Y;

            float refr = 0.f;
            unsigned hb = hist;
            while (hb) { int k = __ffs(hb) - 1; hb &= hb - 1; refr += srefk[k + 1]; }

            bool s = (u + refr >= THETA);
            hist = ((hist << 1) | (s ? 1u : 0u)) & 0x7FFFFFFFu;
            so[t] = s ? 1.0f : 0.0f;
        }
    }
}

// ---------------- launch ----------------
extern "C" void kernel_launch(void* const* d_in, const int* in_sizes, int n_in,
                              void* d_out, int out_size) {
    const float* x  = (const float*)d_in[0];   // [32, 2048, 350]
    const float* W1 = (const float*)d_in[1];   // [512, 2048]
    const float* W2 = (const float*)d_in[2];   // [10, 512]
    float* out = (float*)d_out;                // [32, 10, 350]

    const int SMEM_G1 = 2 * CH * NHID * 4 + TT * NW * 4;   // 71,936 B
    const int SMEM_L1 = (RING * CC * 128 + KREF) * 4;      // 64,128 B
    cudaFuncSetAttribute(k_gemm1, cudaFuncAttributeMaxDynamicSharedMemorySize,
                         SMEM_G1);
    cudaFuncSetAttribute(k_layer1, cudaFuncAttributeMaxDynamicSharedMemorySize,
                         SMEM_L1);

    k_transpose<<<dim3(NIN / 32, NHID / 32), dim3(32, 8)>>>(W1);   // 1
    k_pack<<<dim3(NW, BB), 128>>>(x);                              // 2
    k_dummy<<<1, 32>>>();                                          // 3
    k_gemm1<<<dim3(NWIN, BB), 128, SMEM_G1>>>();                   // 4 (ncu slot)
    k_layer1<<<dim3(NHID / 128, BB), 128, SMEM_L1>>>();            // 5
    k_out<<<BB, 352>>>(W2, out);                                   // 6
}

// round 12
// speedup vs baseline: 2.5673x; 1.1235x over previous
#include <cuda_runtime.h>

#define BB    32
#define NIN   2048
#define NHID  512
#define NOUT  10
#define TLEN  350
#define KSRM  100
#define KREF  32
#define THETA 10.0f
#define TT    25            // timesteps per GEMM1 window (350 = 14*25)
#define NWIN  (TLEN / TT)   // 14
#define NW    (NIN / 32)    // 64
#define HW    (NHID / 32)   // 16
#define CH    16            // weight rows per staged chunk
#define NCHK  (NIN / CH)    // 128
#define TG    13            // t per group (group0: 13, group1: 12)
#define CC    25            // layer1 tile (100 = 4*25)
#define NCH   (TLEN / CC)   // 14
#define RING  5

// ---------------- device scratch ----------------
__device__ float    g_W1T[NIN * NHID];          // 4 MB, W1 transposed [n][m]
__device__ unsigned g_bits1[BB * TLEN * NW];    // packed spikes [b][t][w]
__device__ float    g_z1[BB * TLEN * NHID];     // [b][t][m]
__device__ unsigned g_s1b[BB * TLEN * HW];      // packed layer-1 spikes

extern __shared__ char sm_raw[];

// ---------------- K1: transpose W1 [NHID][NIN] -> [NIN][NHID] ------------
__global__ void k_transpose(const float* __restrict__ W1) {
    __shared__ float tile[32][33];
    int bx = blockIdx.x * 32, by = blockIdx.y * 32;
    int tx = threadIdx.x, ty = threadIdx.y;
    #pragma unroll
    for (int j = 0; j < 32; j += 8)
        tile[ty + j][tx] = W1[(by + ty + j) * NIN + bx + tx];
    __syncthreads();
    #pragma unroll
    for (int j = 0; j < 32; j += 8)
        g_W1T[(bx + ty + j) * NHID + (by + tx)] = tile[tx][ty + j];
}

// ---------------- K0: pack input spikes (float2 over t) ------------------
__global__ void k_pack(const float* __restrict__ x) {
    int b = blockIdx.y;
    int w = blockIdx.x;
    const float* xb = x + ((size_t)b * NIN + w * 32) * TLEN;
    for (int k = threadIdx.x; k < TLEN / 2; k += blockDim.x) {
        int t = k * 2;
        unsigned w0 = 0, w1 = 0;
        #pragma unroll
        for (int j = 0; j < 32; j++) {
            float2 v = *(const float2*)(xb + j * TLEN + t);
            w0 |= (v.x > 0.5f) ? (1u << j) : 0u;
            w1 |= (v.y > 0.5f) ? (1u << j) : 0u;
        }
        g_bits1[(b * TLEN + t    ) * NW + w] = w0;
        g_bits1[(b * TLEN + t + 1) * NW + w] = w1;
    }
}

// ---------------- dummy (ncu launch-slot alignment) ----------------------
__global__ void k_dummy() {}

// ---------------- K2: sparse GEMM, 2 t-groups x 128thr x float4 ----------
// CTA = (window of 25 t, b). 256 threads: group tg=tid>>7 owns a t-range,
// each thread owns 4 adjacent m (float4). Per event only 4 warps issue;
// 24 warps/SM (3 CTAs) hide LDS latency. Double-buffered cp.async staging.
__global__ __launch_bounds__(256, 3) void k_gemm1() {
    float*    stage = (float*)sm_raw;                          // [2][CH*NHID] 64 KB
    unsigned* colm  = (unsigned*)(sm_raw + 2 * CH * NHID * 4); // [TT][NW] 6.25 KB

    int b    = blockIdx.y;
    int t0   = blockIdx.x * TT;
    int tid  = threadIdx.x;
    int tg   = tid >> 7;          // t-group 0/1
    int lid  = tid & 127;         // m-slot (owns m = 4*lid .. 4*lid+3)
    int tbeg = tg * TG;           // group0: t 0..12, group1: t 13..24

    // column masks for this window ([t][w] contiguous in g_bits1)
    for (int i = tid; i < TT * NW; i += 256)
        colm[i] = g_bits1[(b * TLEN + t0) * NW + i];

    float4 acc[TG];
    #pragma unroll
    for (int i = 0; i < TG; i++) acc[i] = make_float4(0.f, 0.f, 0.f, 0.f);

    const char* wsrc = (const char*)g_W1T;

    // cp.async copy of chunk c into buffer c&1 (8 x 16B per thread = 32 KB)
    #define ISSUE_CHUNK(c) do {                                              \
        unsigned _dst = (unsigned)__cvta_generic_to_shared(                  \
            stage + ((c) & 1) * (CH * NHID)) + tid * 16;                     \
        const char* _src = wsrc + (size_t)(c) * (CH * NHID * 4) + tid * 16;  \
        _Pragma("unroll")                                                    \
        for (int k = 0; k < 8; k++)                                          \
            asm volatile("cp.async.cg.shared.global [%0], [%1], 16;"         \
                         :: "r"(_dst + k * 4096), "l"(_src + k * 4096)       \
                         : "memory");                                        \
        asm volatile("cp.async.commit_group;" ::: "memory");                 \
    } while (0)

    ISSUE_CHUNK(0);

    for (int c = 0; c < NCHK; c++) {
        if (c) __syncthreads();            // everyone done reading buf (c+1)&1
        if (c + 1 < NCHK) {
            ISSUE_CHUNK(c + 1);
            asm volatile("cp.async.wait_group 1;" ::: "memory");
        } else {
            asm volatile("cp.async.wait_group 0;" ::: "memory");
        }
        __syncthreads();                   // chunk c (and colm on c==0) visible

        const float4* st = (const float4*)(stage + (c & 1) * (CH * NHID)) + lid;
        int wi = c >> 1, sh = (c & 1) * 16;

        #pragma unroll
        for (int i = 0; i < TG; i++) {
            int t = tbeg + i;
            unsigned m = (t < TT) ? ((colm[t * NW + wi] >> sh) & 0xFFFFu) : 0u;
            while (m) {
                int j = __ffs(m) - 1; m &= m - 1;
                float4 wv = st[j * 128];   // LDS.128, conflict-free
                acc[i].x += wv.x;
                acc[i].y += wv.y;
                acc[i].z += wv.z;
                acc[i].w += wv.w;
            }
        }
    }
    #undef ISSUE_CHUNK

    float4* zo = (float4*)(g_z1 + ((size_t)b * TLEN + t0) * NHID);
    #pragma unroll
    for (int i = 0; i < TG; i++) {
        int t = tbeg + i;
        if (t < TT) zo[t * 128 + lid] = acc[i];    // coalesced 16B stores
    }
}

// ---------------- K3: layer-1 SRM + spike (smem ring) --------------------
__global__ void k_layer1() {
    float* ring  = (float*)sm_raw;                  // [RING][CC*128]
    float* srefk = (float*)sm_raw + RING * CC * 128;

    int b   = blockIdx.y;
    int m0  = blockIdx.x * 128;
    int tid = threadIdx.x;
    if (tid < KREF)
        srefk[tid] = -2.0f * THETA * (float)tid * expf(1.0f - (float)tid);

    const float r    = expf(-0.1f);
    const float rK   = expf(-10.0f);
    const float KrK  = 100.0f * rK;
    const float Ceps = expf(1.0f) * 0.1f;

    const float* zb = g_z1 + (size_t)b * TLEN * NHID + m0;

    float A = 0.f, Y = 0.f;
    unsigned hist = 0;
    int wbase = (b * TLEN) * HW + (m0 >> 5) + (tid >> 5);

    for (int c = 0; c < NCH; c++) {
        float* tile = ring + (c % RING) * (CC * 128);
        __syncthreads();
        #pragma unroll
        for (int i = 0; i < CC; i++)
            tile[i * 128 + tid] = zb[(size_t)(c * CC + i) * NHID + tid];
        __syncthreads();

        const float* tprev = ring + ((c + 1) % RING) * (CC * 128); // slot c-4
        #pragma unroll
        for (int i = 0; i < CC; i++) {
            float xz = tile[i * 128 + tid];
            float xo = (c >= 4) ? tprev[i * 128 + tid] : 0.f;
            float Yn = r * (Y + A) - KrK * xo;
            A = r * A + xz - rK * xo;
            Y = Yn;
            float u = Ceps * Y;

            float refr = 0.f;
            unsigned hb = hist;
            while (hb) { int k = __ffs(hb) - 1; hb &= hb - 1; refr += srefk[k + 1]; }

            bool s = (u + refr >= THETA);
            hist = ((hist << 1) | (s ? 1u : 0u)) & 0x7FFFFFFFu;

            unsigned bal = __ballot_sync(0xFFFFFFFFu, s);
            if ((tid & 31) == 0)
                g_s1b[wbase + (c * CC + i) * HW] = bal;
        }
    }
}

// ---------------- K4: fused gemm2 + layer-2 SRM + spike ------------------
__global__ __launch_bounds__(352) void k_out(const float* __restrict__ W2,
                                             float* __restrict__ out) {
    __shared__ float w2t[NHID * NOUT];
    __shared__ float q[NOUT * TLEN];
    __shared__ float srefk[KREF];

    int b = blockIdx.x, tid = threadIdx.x;
    for (int i = tid; i < NHID * NOUT; i += blockDim.x) {
        int o = i / NHID, m = i % NHID;
        w2t[m * NOUT + o] = W2[i];
    }
    if (tid < KREF)
        srefk[tid] = -2.0f * THETA * (float)tid * expf(1.0f - (float)tid);
    __syncthreads();

    if (tid < TLEN) {
        int t = tid;
        float a[NOUT];
        #pragma unroll
        for (int o = 0; o < NOUT; o++) a[o] = 0.f;
        #pragma unroll
        for (int w = 0; w < HW; w++) {
            unsigned bits = g_s1b[(b * TLEN + t) * HW + w];
            while (bits) {
                int m = w * 32 + __ffs(bits) - 1;
                bits &= bits - 1;
                #pragma unroll
                for (int o = 0; o < NOUT; o++) a[o] += w2t[m * NOUT + o];
            }
        }
        #pragma unroll
        for (int o = 0; o < NOUT; o++) q[o * TLEN + t] = a[o];
    }
    __syncthreads();

    if (tid < NOUT) {
        const float r    = expf(-0.1f);
        const float rK   = expf(-10.0f);
        const float KrK  = 100.0f * rK;
        const float Ceps = expf(1.0f) * 0.1f;

        const float* qq = q + tid * TLEN;
        float* so = out + ((size_t)b * NOUT + tid) * TLEN;

        float A = 0.f, Y = 0.f;
        unsigned hist = 0;
        for (int t = 0; t < TLEN; t++) {
            float xz = qq[t];
            float xo = (t >= KSRM) ? qq[t - KSRM] : 0.f;
            float Yn = r * (Y + A) - KrK * xo;
            A = r * A + xz - rK * xo;
            Y = Yn;
            float u = Ceps * Y;

            float refr = 0.f;
            unsigned hb = hist;
            while (hb) { int k = __ffs(hb) - 1; hb &= hb - 1; refr += srefk[k + 1]; }

            bool s = (u + refr >= THETA);
            hist = ((hist << 1) | (s ? 1u : 0u)) & 0x7FFFFFFFu;
            so[t] = s ? 1.0f : 0.0f;
        }
    }
}

// ---------------- launch ----------------
extern "C" void kernel_launch(void* const* d_in, const int* in_sizes, int n_in,
                              void* d_out, int out_size) {
    const float* x  = (const float*)d_in[0];   // [32, 2048, 350]
    const float* W1 = (const float*)d_in[1];   // [512, 2048]
    const float* W2 = (const float*)d_in[2];   // [10, 512]
    float* out = (float*)d_out;                // [32, 10, 350]

    const int SMEM_G1 = 2 * CH * NHID * 4 + TT * NW * 4;   // 71,936 B
    const int SMEM_L1 = (RING * CC * 128 + KREF) * 4;      // 64,128 B
    cudaFuncSetAttribute(k_gemm1, cudaFuncAttributeMaxDynamicSharedMemorySize,
                         SMEM_G1);
    cudaFuncSetAttribute(k_layer1, cudaFuncAttributeMaxDynamicSharedMemorySize,
                         SMEM_L1);

    k_transpose<<<dim3(NIN / 32, NHID / 32), dim3(32, 8)>>>(W1);   // 1
    k_pack<<<dim3(NW, BB), 128>>>(x);                              // 2
    k_dummy<<<1, 32>>>();                                          // 3
    k_gemm1<<<dim3(NWIN, BB), 256, SMEM_G1>>>();                   // 4 (ncu slot)
    k_layer1<<<dim3(NHID / 128, BB), 128, SMEM_L1>>>();            // 5
    k_out<<<BB, 352>>>(W2, out);                                   // 6
}